// round 1
// baseline (speedup 1.0000x reference)
#include <cuda_runtime.h>

#define BB   32      // batch
#define NN   2048    // input capsules
#define IL   32      // input capsule length
#define CC   32      // output capsules
#define LL   32      // output capsule length
#define KK   1024    // CC*LL
#define NCH1 128     // j-chunks for u/s0 kernel
#define JPC1 16      // j per chunk (K1)
#define NCH2 16      // j-chunks for routing passes
#define JP2  128     // j per chunk (pass)

typedef unsigned long long ull;

// Scratch (device globals: allocation-free rule)
__device__ float g_u  [(size_t)BB * NN * KK];     // 256 MB prediction tensor
__device__ float g_s0p[(size_t)BB * NCH1 * KK];   // s partials, round 0
__device__ float g_sp [(size_t)BB * NCH2 * KK];   // s partials, rounds 1/2
__device__ float g_v0 [BB * KK];
__device__ float g_v1 [BB * KK];

__device__ __forceinline__ void ffma2(ull& acc, ull a, ull b) {
    asm("fma.rn.f32x2 %0, %1, %2, %0;" : "+l"(acc) : "l"(a), "l"(b));
}
__device__ __forceinline__ void fadd2(ull& acc, ull a) {
    asm("add.rn.f32x2 %0, %1, %0;" : "+l"(acc) : "l"(a));
}
__device__ __forceinline__ float2 up2(ull v) {
    float2 f;
    asm("mov.b64 {%0, %1}, %2;" : "=f"(f.x), "=f"(f.y) : "l"(v));
    return f;
}

// K1: u[b,j,k] = sum_i x[b,j,i] * W[j,i,k]; also s0 partial = sum_j u / 32.
// CTA = (j-chunk, k-quarter); all 32 b held in per-thread registers so W
// streams through the SM exactly once (LTS cap is path-independent).
// Thread: kg = tid&63 (4 consecutive k), bg = tid>>6 (8 b's). FFMA2 packed.
__global__ void __launch_bounds__(256, 2)
k1(const float* __restrict__ x, const float* __restrict__ Wt) {
    const int kg    = threadIdx.x & 63;
    const int bg    = threadIdx.x >> 6;
    const int chunk = blockIdx.x;
    const int kq    = blockIdx.y;          // 0..3, 256 k each
    __shared__ float2 xs2[32][32];         // x duplicated into f32x2 lanes

    ull s0[8][2];
#pragma unroll
    for (int bb = 0; bb < 8; bb++) { s0[bb][0] = 0ull; s0[bb][1] = 0ull; }

    for (int jj = 0; jj < JPC1; jj++) {
        const int j = chunk * JPC1 + jj;
        __syncthreads();
#pragma unroll
        for (int r = 0; r < 4; r++) {
            int idx = threadIdx.x + 256 * r;
            int b = idx >> 5, i = idx & 31;
            float v = x[((size_t)b * NN + j) * IL + i];
            xs2[b][i] = make_float2(v, v);
        }
        __syncthreads();

        const ulonglong2* Wj =
            reinterpret_cast<const ulonglong2*>(Wt + (size_t)j * IL * KK) +
            (size_t)kq * 64 + kg;

        ull acc[8][2];
#pragma unroll
        for (int bb = 0; bb < 8; bb++) { acc[bb][0] = 0ull; acc[bb][1] = 0ull; }

#pragma unroll
        for (int i = 0; i < IL; i++) {
            ulonglong2 w = Wj[(size_t)i * 256];   // W[j,i, kq*256+kg*4 .. +3]
#pragma unroll
            for (int bb = 0; bb < 8; bb++) {
                ull xx = *reinterpret_cast<const ull*>(&xs2[bg * 8 + bb][i]);
                ffma2(acc[bb][0], w.x, xx);
                ffma2(acc[bb][1], w.y, xx);
            }
        }

        const size_t kbase = (size_t)kq * 256 + (size_t)kg * 4;
#pragma unroll
        for (int bb = 0; bb < 8; bb++) {
            const int b = bg * 8 + bb;
            float2 a0 = up2(acc[bb][0]), a1 = up2(acc[bb][1]);
            float4 r = make_float4(a0.x, a0.y, a1.x, a1.y);
            *reinterpret_cast<float4*>(g_u + ((size_t)b * NN + j) * KK + kbase) = r;
            fadd2(s0[bb][0], acc[bb][0]);
            fadd2(s0[bb][1], acc[bb][1]);
        }
    }

    const float sc = 1.0f / 32.0f;   // softmax(0) coupling = 1/C
#pragma unroll
    for (int bb = 0; bb < 8; bb++) {
        const int b = bg * 8 + bb;
        float2 a0 = up2(s0[bb][0]), a1 = up2(s0[bb][1]);
        float4 r = make_float4(a0.x * sc, a0.y * sc, a1.x * sc, a1.y * sc);
        *reinterpret_cast<float4*>(
            g_s0p + ((size_t)b * NCH1 + chunk) * KK + (size_t)kq * 256 + (size_t)kg * 4) = r;
    }
}

// Routing pass: single sweep over u fusing logit update + softmax + s accum.
// NP=1: logits = u.v0 (round 0->1). NP=2: logits = u.v0 + u.v1 (round 1->2).
// Thread t owns k = 4t (so c = t>>3, 8 threads per c). Softmax across C via
// 8-lane shfl partial dot + warp-0 smem softmax.
template <int NP>
__global__ void __launch_bounds__(256)
k_pass(const float* __restrict__ vin0, const float* __restrict__ vin1,
       float* __restrict__ sp) {
    const int t = threadIdx.x;
    const int b = blockIdx.y;
    const int chunk = blockIdx.x;
    const int c = t >> 3;

    const float4 v0r = *reinterpret_cast<const float4*>(vin0 + (size_t)b * KK + 4 * t);
    float4 v1r = make_float4(0.f, 0.f, 0.f, 0.f);
    if (NP == 2)
        v1r = *reinterpret_cast<const float4*>(vin1 + (size_t)b * KK + 4 * t);

    __shared__ float db_s[CC];
    __shared__ float cc_s[CC];

    float4 sacc = make_float4(0.f, 0.f, 0.f, 0.f);
    const float* ub = g_u + ((size_t)b * NN + (size_t)chunk * JP2) * KK + 4 * t;
    float4 uu = *reinterpret_cast<const float4*>(ub);

    for (int jj = 0; jj < JP2; jj++) {
        float4 un = uu;
        if (jj + 1 < JP2)   // prefetch next row before the barriers
            un = *reinterpret_cast<const float4*>(ub + (size_t)(jj + 1) * KK);

        float d = uu.x * v0r.x + uu.y * v0r.y + uu.z * v0r.z + uu.w * v0r.w;
        if (NP == 2)
            d += uu.x * v1r.x + uu.y * v1r.y + uu.z * v1r.z + uu.w * v1r.w;
        d += __shfl_xor_sync(0xffffffffu, d, 1);
        d += __shfl_xor_sync(0xffffffffu, d, 2);
        d += __shfl_xor_sync(0xffffffffu, d, 4);
        if ((t & 7) == 0) db_s[c] = d;
        __syncthreads();
        if (t < 32) {
            float dd = db_s[t];
            float mx = dd;
#pragma unroll
            for (int o = 16; o; o >>= 1) mx = fmaxf(mx, __shfl_xor_sync(0xffffffffu, mx, o));
            float e = __expf(dd - mx);
            float se = e;
#pragma unroll
            for (int o = 16; o; o >>= 1) se += __shfl_xor_sync(0xffffffffu, se, o);
            cc_s[t] = e / se;
        }
        __syncthreads();
        const float cc = cc_s[c];
        sacc.x += cc * uu.x; sacc.y += cc * uu.y;
        sacc.z += cc * uu.z; sacc.w += cc * uu.w;
        uu = un;
    }
    *reinterpret_cast<float4*>(sp + ((size_t)b * NCH2 + chunk) * KK + 4 * t) = sacc;
}

// Finalize: reduce chunk partials + biases, squash -> v. One warp per (b,c).
template <int NCH>
__global__ void __launch_bounds__(256)
k_fin(const float* __restrict__ sp, const float* __restrict__ biases,
      float* __restrict__ vout) {
    const int gw = blockIdx.x * 8 + (threadIdx.x >> 5);
    const int lane = threadIdx.x & 31;
    const int b = gw >> 5, c = gw & 31;

    float s = biases[c * LL + lane];
    const float* p = sp + (size_t)b * NCH * KK + c * LL + lane;
#pragma unroll 8
    for (int n = 0; n < NCH; n++) s += p[(size_t)n * KK];

    float n2 = s * s;
#pragma unroll
    for (int o = 16; o; o >>= 1) n2 += __shfl_xor_sync(0xffffffffu, n2, o);
    const float nn = sqrtf(n2);
    const float f = n2 / (1.0f + n2) / (nn + 1e-7f);   // squash factor
    vout[(size_t)b * KK + c * LL + lane] = f * s;
}

extern "C" void kernel_launch(void* const* d_in, const int* in_sizes, int n_in,
                              void* d_out, int out_size) {
    const float* x      = (const float*)d_in[0];  // [32,8,8,32,32] = [B,N,iL]
    const float* Wt     = (const float*)d_in[1];  // [2048,32,1024]
    const float* biases = (const float*)d_in[2];  // [32,32]
    float* out = (float*)d_out;                   // [32,32,32]

    float *s0p, *sp, *v0, *v1;
    cudaGetSymbolAddress((void**)&s0p, g_s0p);
    cudaGetSymbolAddress((void**)&sp,  g_sp);
    cudaGetSymbolAddress((void**)&v0,  g_v0);
    cudaGetSymbolAddress((void**)&v1,  g_v1);

    // u + s0 partials (round 0 couplings are uniform 1/C)
    k1<<<dim3(NCH1, 4), 256>>>(x, Wt);
    // v0 = squash(s0 + biases)
    k_fin<NCH1><<<BB * CC / 8, 256>>>(s0p, biases, v0);
    // round 0->1: logits = u.v0, softmax, s1 partials
    k_pass<1><<<dim3(NCH2, BB), 256>>>(v0, v0, sp);
    k_fin<NCH2><<<BB * CC / 8, 256>>>(sp, biases, v1);
    // round 1->2: logits = u.v0 + u.v1, softmax, s2 partials
    k_pass<2><<<dim3(NCH2, BB), 256>>>(v0, v1, sp);
    // final v -> output
    k_fin<NCH2><<<BB * CC / 8, 256>>>(sp, biases, out);
}

// round 3
// speedup vs baseline: 1.2101x; 1.2101x over previous
#include <cuda_runtime.h>
#include <cuda_fp16.h>

#define BB   32      // batch
#define NN   2048    // input capsules
#define IL   32      // input capsule length
#define CC   32      // output capsules
#define LL   32      // output capsule length
#define KK   1024    // CC*LL
#define NCH1 128     // j-chunks for u/s0 kernel
#define JPC1 16      // j per chunk (K1)
#define PCH  64      // pass CTAs per b (each CTA covers 32 j)
#define JPW  8       // j per warp in pass

typedef unsigned long long ull;

// Scratch (device globals: allocation-free rule)
__device__ __half g_uh [(size_t)BB * NN * KK];    // 128 MB prediction tensor (fp16)
__device__ float  g_s0p[(size_t)BB * NCH1 * KK];  // s partials, round 0 (16 MB)
__device__ float  g_sp [(size_t)BB * PCH * KK];   // s partials, rounds 1/2 (8 MB)
__device__ float  g_v0 [BB * KK];
__device__ float  g_v1 [BB * KK];
__device__ float  g_dummy[1];

__device__ __forceinline__ void ffma2(ull& acc, ull a, ull b) {
    asm("fma.rn.f32x2 %0, %1, %2, %0;" : "+l"(acc) : "l"(a), "l"(b));
}
__device__ __forceinline__ void fadd2(ull& acc, ull a) {
    asm("add.rn.f32x2 %0, %1, %0;" : "+l"(acc) : "l"(a));
}
__device__ __forceinline__ float2 up2(ull v) {
    float2 f;
    asm("mov.b64 {%0, %1}, %2;" : "=f"(f.x), "=f"(f.y) : "l"(v));
    return f;
}

// Launch-ordering shim: makes the ncu-profiled launch (#5, 0-based) land on
// k_pass<2> instead of the trivial finalize.
__global__ void k_dummy(float* p) { if (threadIdx.x == 0) p[0] = 0.f; }

// K1: u[b,j,k] = sum_i x[b,j,i] * W[j,i,k]; also s0 partial = sum_j u / 32.
// CTA = (j-chunk, k-quarter); all 32 b held in per-thread registers so W
// streams through the SM exactly once. FFMA2-packed; u stored fp16.
__global__ void __launch_bounds__(256, 2)
k1(const float* __restrict__ x, const float* __restrict__ Wt) {
    const int kg    = threadIdx.x & 63;
    const int bg    = threadIdx.x >> 6;
    const int chunk = blockIdx.x;
    const int kq    = blockIdx.y;          // 0..3, 256 k each
    __shared__ float2 xs2[32][32];         // x duplicated into f32x2 lanes

    ull s0[8][2];
#pragma unroll
    for (int bb = 0; bb < 8; bb++) { s0[bb][0] = 0ull; s0[bb][1] = 0ull; }

    for (int jj = 0; jj < JPC1; jj++) {
        const int j = chunk * JPC1 + jj;
        __syncthreads();
#pragma unroll
        for (int r = 0; r < 4; r++) {
            int idx = threadIdx.x + 256 * r;
            int b = idx >> 5, i = idx & 31;
            float v = x[((size_t)b * NN + j) * IL + i];
            xs2[b][i] = make_float2(v, v);
        }
        __syncthreads();

        const ulonglong2* Wj =
            reinterpret_cast<const ulonglong2*>(Wt + (size_t)j * IL * KK) +
            (size_t)kq * 64 + kg;

        ull acc[8][2];
#pragma unroll
        for (int bb = 0; bb < 8; bb++) { acc[bb][0] = 0ull; acc[bb][1] = 0ull; }

#pragma unroll
        for (int i = 0; i < IL; i += 2) {
            ulonglong2 w0 = Wj[(size_t)i * 256];
            ulonglong2 w1 = Wj[(size_t)(i + 1) * 256];
#pragma unroll
            for (int bb = 0; bb < 8; bb++) {
                // one LDS.128 fetches the duplicated x_i and x_{i+1} pair
                ulonglong2 xx = *reinterpret_cast<const ulonglong2*>(&xs2[bg * 8 + bb][i]);
                ffma2(acc[bb][0], w0.x, xx.x);
                ffma2(acc[bb][1], w0.y, xx.x);
                ffma2(acc[bb][0], w1.x, xx.y);
                ffma2(acc[bb][1], w1.y, xx.y);
            }
        }

        const size_t kbase = (size_t)kq * 256 + (size_t)kg * 4;
#pragma unroll
        for (int bb = 0; bb < 8; bb++) {
            const int b = bg * 8 + bb;
            float2 a0 = up2(acc[bb][0]), a1 = up2(acc[bb][1]);
            __half2 h0 = __floats2half2_rn(a0.x, a0.y);
            __half2 h1 = __floats2half2_rn(a1.x, a1.y);
            uint2 pk;
            pk.x = *reinterpret_cast<unsigned*>(&h0);
            pk.y = *reinterpret_cast<unsigned*>(&h1);
            *reinterpret_cast<uint2*>(g_uh + ((size_t)b * NN + j) * KK + kbase) = pk;
            fadd2(s0[bb][0], acc[bb][0]);   // s0 stays fp32 (round-0 precision)
            fadd2(s0[bb][1], acc[bb][1]);
        }
    }

    const float sc = 1.0f / 32.0f;   // softmax(0) coupling = 1/C
#pragma unroll
    for (int bb = 0; bb < 8; bb++) {
        const int b = bg * 8 + bb;
        float2 a0 = up2(s0[bb][0]), a1 = up2(s0[bb][1]);
        float4 r = make_float4(a0.x * sc, a0.y * sc, a1.x * sc, a1.y * sc);
        *reinterpret_cast<float4*>(
            g_s0p + ((size_t)b * NCH1 + chunk) * KK + (size_t)kq * 256 + (size_t)kg * 4) = r;
    }
}

// Stage one u row (512 uints) into padded smem: uint m -> pos m + (m>>4).
// Row c (k = c*32 .. c*32+31) then lives at positions c*17 + w (w=0..15),
// and c*17 mod 32 is a permutation of c -> conflict-free row reads.
__device__ __forceinline__ void stage_row(unsigned* s, const uint4* r, int c) {
#pragma unroll
    for (int q = 0; q < 4; q++) {
        const unsigned* e = reinterpret_cast<const unsigned*>(&r[q]);
#pragma unroll
        for (int ee = 0; ee < 4; ee++) {
            int m = 4 * (c + 32 * q) + ee;
            s[m + (m >> 4)] = e[ee];
        }
    }
}

// Routing pass, warp-per-j, no CTA barriers in the main loop.
// Lane c OWNS output capsule c: after the padded-smem transpose it reads
// u[j, c*32 + l] for l=0..31, computes the logit dot vs v[c] in registers,
// does the softmax over C via 32-lane shfl, accumulates s[c*32+l] locally.
// NP=1: logits = u.v0. NP=2: logits = u.(v0+v1).
template <int NP>
__global__ void __launch_bounds__(128)
k_pass(const float* __restrict__ vin0, const float* __restrict__ vin1,
       float* __restrict__ sp) {
    const int b    = blockIdx.y;
    const int warp = threadIdx.x >> 5;
    const int c    = threadIdx.x & 31;

    __shared__ unsigned us[4][544];         // padded per-warp u-row stage
    __shared__ float red[4][CC * 33];       // padded CTA reduction buffer

    // v row for this lane's c (NP==2 folds v0+v1 into one dot vector)
    float vv[32];
#pragma unroll
    for (int q = 0; q < 8; q++) {
        float4 t = *reinterpret_cast<const float4*>(vin0 + (size_t)b * KK + c * LL + q * 4);
        if (NP == 2) {
            float4 t1 = *reinterpret_cast<const float4*>(vin1 + (size_t)b * KK + c * LL + q * 4);
            t.x += t1.x; t.y += t1.y; t.z += t1.z; t.w += t1.w;
        }
        vv[q * 4 + 0] = t.x; vv[q * 4 + 1] = t.y; vv[q * 4 + 2] = t.z; vv[q * 4 + 3] = t.w;
    }

    float sacc[32];
#pragma unroll
    for (int l = 0; l < 32; l++) sacc[l] = 0.f;

    const int jbase = blockIdx.x * 32 + warp * JPW;
    const __half* urow0 = g_uh + ((size_t)b * NN + jbase) * KK;

    // stage j0 (coalesced LDG: thread c takes uint4 c+32q of the row)
    uint4 r[4];
    {
        const uint4* up = reinterpret_cast<const uint4*>(urow0);
#pragma unroll
        for (int q = 0; q < 4; q++) r[q] = up[c + 32 * q];
    }
    stage_row(us[warp], r, c);
    __syncwarp();

    for (int jj = 0; jj < JPW; jj++) {
        // read my row c from smem (conflict-free), convert to fp32
        float uf[32];
#pragma unroll
        for (int w = 0; w < 16; w++) {
            unsigned t = us[warp][c * 17 + w];
            float2 f = __half22float2(*reinterpret_cast<const __half2*>(&t));
            uf[2 * w] = f.x; uf[2 * w + 1] = f.y;
        }

        // prefetch next j and restage (after all lanes finished reading)
        if (jj + 1 < JPW) {
            const uint4* up = reinterpret_cast<const uint4*>(urow0 + (size_t)(jj + 1) * KK);
#pragma unroll
            for (int q = 0; q < 4; q++) r[q] = up[c + 32 * q];
        }
        __syncwarp();
        if (jj + 1 < JPW) stage_row(us[warp], r, c);
        __syncwarp();

        // logit for capsule c
        float d0 = 0.f, d1 = 0.f, d2 = 0.f, d3 = 0.f;
#pragma unroll
        for (int l = 0; l < 32; l += 4) {
            d0 += uf[l + 0] * vv[l + 0];
            d1 += uf[l + 1] * vv[l + 1];
            d2 += uf[l + 2] * vv[l + 2];
            d3 += uf[l + 3] * vv[l + 3];
        }
        float d = (d0 + d1) + (d2 + d3);

        // softmax over the 32 c's (one per lane)
        float mx = d;
#pragma unroll
        for (int o = 16; o; o >>= 1) mx = fmaxf(mx, __shfl_xor_sync(0xffffffffu, mx, o));
        float e = __expf(d - mx);
        float se = e;
#pragma unroll
        for (int o = 16; o; o >>= 1) se += __shfl_xor_sync(0xffffffffu, se, o);
        const float cc = e / se;

#pragma unroll
        for (int l = 0; l < 32; l++) sacc[l] += cc * uf[l];
    }

    // CTA-level reduction of the 4 warp partials (padded smem, conflict-free)
#pragma unroll
    for (int l = 0; l < 32; l++) red[warp][c * 33 + l] = sacc[l];
    __syncthreads();

    // 128 threads x 8 k each, coalesced float writeout of the CTA partial
    const int t = threadIdx.x;
#pragma unroll
    for (int q = 0; q < 8; q++) {
        int k = t * 8 + q;
        int kc = k >> 5, kl = k & 31;
        float s = red[0][kc * 33 + kl] + red[1][kc * 33 + kl]
                + red[2][kc * 33 + kl] + red[3][kc * 33 + kl];
        sp[((size_t)b * PCH + blockIdx.x) * KK + k] = s;
    }
}

// Finalize: reduce chunk partials + biases, squash -> v. One warp per (b,c).
template <int NCH>
__global__ void __launch_bounds__(256)
k_fin(const float* __restrict__ sp, const float* __restrict__ biases,
      float* __restrict__ vout) {
    const int gw = blockIdx.x * 8 + (threadIdx.x >> 5);
    const int lane = threadIdx.x & 31;
    const int b = gw >> 5, c = gw & 31;

    float s = biases[c * LL + lane];
    const float* p = sp + (size_t)b * NCH * KK + c * LL + lane;
#pragma unroll 8
    for (int n = 0; n < NCH; n++) s += p[(size_t)n * KK];

    float n2 = s * s;
#pragma unroll
    for (int o = 16; o; o >>= 1) n2 += __shfl_xor_sync(0xffffffffu, n2, o);
    const float nn = sqrtf(n2);
    const float f = n2 / (1.0f + n2) / (nn + 1e-7f);   // squash factor
    vout[(size_t)b * KK + c * LL + lane] = f * s;
}

extern "C" void kernel_launch(void* const* d_in, const int* in_sizes, int n_in,
                              void* d_out, int out_size) {
    const float* x      = (const float*)d_in[0];  // [32,8,8,32,32] = [B,N,iL]
    const float* Wt     = (const float*)d_in[1];  // [2048,32,1024]
    const float* biases = (const float*)d_in[2];  // [32,32]
    float* out = (float*)d_out;                   // [32,32,32]

    float *s0p, *sp, *v0, *v1, *dm;
    cudaGetSymbolAddress((void**)&s0p, g_s0p);
    cudaGetSymbolAddress((void**)&sp,  g_sp);
    cudaGetSymbolAddress((void**)&v0,  g_v0);
    cudaGetSymbolAddress((void**)&v1,  g_v1);
    cudaGetSymbolAddress((void**)&dm,  g_dummy);

    k_dummy<<<1, 32>>>(dm);                              // launch 0 (ncu shim)
    k1<<<dim3(NCH1, 4), 256>>>(x, Wt);                   // launch 1
    k_fin<NCH1><<<BB * CC / 8, 256>>>(s0p, biases, v0);  // launch 2
    k_pass<1><<<dim3(PCH, BB), 128>>>(v0, v0, sp);       // launch 3
    k_fin<PCH><<<BB * CC / 8, 256>>>(sp, biases, v1);    // launch 4
    k_pass<2><<<dim3(PCH, BB), 128>>>(v0, v1, sp);       // launch 5 <- profiled
    k_fin<PCH><<<BB * CC / 8, 256>>>(sp, biases, out);   // launch 6
}

// round 4
// speedup vs baseline: 2.1126x; 1.7458x over previous
#include <cuda_runtime.h>
#include <cuda_fp16.h>

#define BB   32      // batch
#define NN   2048    // input capsules
#define IL   32      // input capsule length
#define CC   32      // output capsules
#define LL   32      // output capsule length
#define KK   1024    // CC*LL
#define NCH1 512     // j-chunks for u/s0 kernel
#define JPC1 4       // j per chunk (K1)
#define PCH  32      // pass CTAs per b (each CTA covers 64 j)

typedef unsigned long long ull;

// Scratch (device globals: allocation-free rule)
__device__ __half g_uh [(size_t)BB * NN * KK];    // 128 MB prediction tensor (fp16)
__device__ float  g_s0p[(size_t)BB * NCH1 * KK];  // s partials, round 0 (64 MB)
__device__ float  g_sp [(size_t)BB * PCH * KK];   // s partials, rounds 1/2 (4 MB)
__device__ float  g_v0 [BB * KK];
__device__ float  g_v1 [BB * KK];
__device__ float  g_dummy[1];

__device__ __forceinline__ void ffma2(ull& acc, ull a, ull b) {
    asm("fma.rn.f32x2 %0, %1, %2, %0;" : "+l"(acc) : "l"(a), "l"(b));
}
__device__ __forceinline__ void fadd2(ull& acc, ull a) {
    asm("add.rn.f32x2 %0, %1, %0;" : "+l"(acc) : "l"(a));
}
__device__ __forceinline__ float2 up2(ull v) {
    float2 f;
    asm("mov.b64 {%0, %1}, %2;" : "=f"(f.x), "=f"(f.y) : "l"(v));
    return f;
}

__global__ void k_dummy(float* p) { if (threadIdx.x == 0) p[0] = 0.f; }

// K1: u[b,j,k] = sum_i x[b,j,i]*W[j,i,k]; s0 partial = sum_j u / 32.
// CTA = (4-j chunk, k-quarter). x staged ONCE (no barriers in j loop).
// W streamed via explicit ring-4 register pipeline (8 LDG.128 in flight).
__global__ void __launch_bounds__(256, 2)
k1(const float* __restrict__ x, const float* __restrict__ Wt) {
    const int kg    = threadIdx.x & 63;
    const int bg    = threadIdx.x >> 6;
    const int chunk = blockIdx.x;
    const int kq    = blockIdx.y;          // 0..3, 256 k each
    __shared__ float2 xs[JPC1][32][32];    // 32 KB x duplicated for f32x2

    // stage x for the chunk's 4 j's: 4096 float2, 16 per thread
#pragma unroll
    for (int r = 0; r < 16; r++) {
        int idx = threadIdx.x + 256 * r;
        int jl = idx >> 10, rem = idx & 1023;
        int b = rem >> 5, i = rem & 31;
        float v = x[((size_t)b * NN + chunk * JPC1 + jl) * IL + i];
        xs[jl][b][i] = make_float2(v, v);
    }
    __syncthreads();

    // W base for this CTA's quarter; pair p -> (j = p>>4, i = 2*(p&15))
    const ulonglong2* Wb =
        reinterpret_cast<const ulonglong2*>(Wt) +
        (size_t)chunk * JPC1 * IL * 256 + (size_t)kq * 64 + kg;
#define PADDR(p) (Wb + ((size_t)((p) >> 4) * 8192 + (size_t)((p) & 15) * 512))

    ulonglong2 rw0[4], rw1[4];             // ring-4 of W pairs
#pragma unroll
    for (int pp = 0; pp < 4; pp++) { rw0[pp] = PADDR(pp)[0]; rw1[pp] = PADDR(pp)[256]; }

    ull acc[8][2], s0[8][2];
#pragma unroll
    for (int bb = 0; bb < 8; bb++) {
        acc[bb][0] = acc[bb][1] = 0ull;
        s0[bb][0] = s0[bb][1] = 0ull;
    }

    for (int j = 0; j < JPC1; j++) {
#pragma unroll
        for (int pr = 0; pr < 16; pr++) {
            const int p = j * 16 + pr;
            const int s = pr & 3;          // ring slot (16 % 4 == 0)
            ulonglong2 w0 = rw0[s], w1 = rw1[s];
            if (p + 4 < 64) { rw0[s] = PADDR(p + 4)[0]; rw1[s] = PADDR(p + 4)[256]; }
            const int i = pr * 2;
#pragma unroll
            for (int bb = 0; bb < 8; bb++) {
                ulonglong2 xx = *reinterpret_cast<const ulonglong2*>(&xs[j][bg * 8 + bb][i]);
                ffma2(acc[bb][0], w0.x, xx.x);
                ffma2(acc[bb][1], w0.y, xx.x);
                ffma2(acc[bb][0], w1.x, xx.y);
                ffma2(acc[bb][1], w1.y, xx.y);
            }
        }
        // store u row (fp16), fold into s0, reset acc
        const size_t kbase = (size_t)kq * 256 + (size_t)kg * 4;
        const int jg = chunk * JPC1 + j;
#pragma unroll
        for (int bb = 0; bb < 8; bb++) {
            const int b = bg * 8 + bb;
            float2 a0 = up2(acc[bb][0]), a1 = up2(acc[bb][1]);
            __half2 h0 = __floats2half2_rn(a0.x, a0.y);
            __half2 h1 = __floats2half2_rn(a1.x, a1.y);
            uint2 pk;
            pk.x = *reinterpret_cast<unsigned*>(&h0);
            pk.y = *reinterpret_cast<unsigned*>(&h1);
            *reinterpret_cast<uint2*>(g_uh + ((size_t)b * NN + jg) * KK + kbase) = pk;
            fadd2(s0[bb][0], acc[bb][0]);
            fadd2(s0[bb][1], acc[bb][1]);
            acc[bb][0] = acc[bb][1] = 0ull;
        }
    }
#undef PADDR

    const float sc = 1.0f / 32.0f;         // softmax(0) coupling = 1/C
    const size_t kbase = (size_t)kq * 256 + (size_t)kg * 4;
#pragma unroll
    for (int bb = 0; bb < 8; bb++) {
        const int b = bg * 8 + bb;
        float2 a0 = up2(s0[bb][0]), a1 = up2(s0[bb][1]);
        float4 r = make_float4(a0.x * sc, a0.y * sc, a1.x * sc, a1.y * sc);
        *reinterpret_cast<float4*>(
            g_s0p + ((size_t)b * NCH1 + chunk) * KK + kbase) = r;
    }
}

// Routing pass, transpose-free. Lane t's uint4 group q (index t+32q of the
// u row) covers k = 8t+256q+e (e<8), all inside capsule c_q = (t>>2)+8q.
// Quad shfl (xor 1,2) completes each capsule dot; shfl xor 4,8,16 spans all
// 32 capsules for the softmax. v is loaded at the SAME k indices, so the
// whole pass runs in natural coalesced layout with zero smem in the loop.
// NP=1: logits = u.v0.   NP=2: logits = u.(v0+v1).
#define PASS_BODY(BUF, JJ)                                                     \
    {                                                                          \
        float uf[32];                                                          \
        _Pragma("unroll")                                                      \
        for (int q = 0; q < 4; q++) {                                          \
            float2 f;                                                          \
            f = __half22float2(*reinterpret_cast<const __half2*>(&BUF[q].x));  \
            uf[8 * q + 0] = f.x; uf[8 * q + 1] = f.y;                          \
            f = __half22float2(*reinterpret_cast<const __half2*>(&BUF[q].y));  \
            uf[8 * q + 2] = f.x; uf[8 * q + 3] = f.y;                          \
            f = __half22float2(*reinterpret_cast<const __half2*>(&BUF[q].z));  \
            uf[8 * q + 4] = f.x; uf[8 * q + 5] = f.y;                          \
            f = __half22float2(*reinterpret_cast<const __half2*>(&BUF[q].w));  \
            uf[8 * q + 6] = f.x; uf[8 * q + 7] = f.y;                          \
        }                                                                      \
        if ((JJ) + 2 < 8) {                                                    \
            _Pragma("unroll")                                                  \
            for (int q = 0; q < 4; q++)                                        \
                BUF[q] = up[((JJ) + 2) * 128 + q * 32 + t];                    \
        }                                                                      \
        float d[4];                                                            \
        _Pragma("unroll")                                                      \
        for (int q = 0; q < 4; q++) {                                          \
            float a = 0.f, bq = 0.f;                                           \
            _Pragma("unroll")                                                  \
            for (int e = 0; e < 8; e += 2) {                                   \
                a  += uf[8 * q + e]     * vv[8 * q + e];                       \
                bq += uf[8 * q + e + 1] * vv[8 * q + e + 1];                   \
            }                                                                  \
            d[q] = a + bq;                                                     \
            d[q] += __shfl_xor_sync(0xffffffffu, d[q], 1);                     \
            d[q] += __shfl_xor_sync(0xffffffffu, d[q], 2);                     \
        }                                                                      \
        float m = fmaxf(fmaxf(d[0], d[1]), fmaxf(d[2], d[3]));                 \
        m = fmaxf(m, __shfl_xor_sync(0xffffffffu, m, 4));                      \
        m = fmaxf(m, __shfl_xor_sync(0xffffffffu, m, 8));                      \
        m = fmaxf(m, __shfl_xor_sync(0xffffffffu, m, 16));                     \
        float ce[4];                                                           \
        _Pragma("unroll")                                                      \
        for (int q = 0; q < 4; q++) ce[q] = __expf(d[q] - m);                  \
        float Z = (ce[0] + ce[1]) + (ce[2] + ce[3]);                           \
        Z += __shfl_xor_sync(0xffffffffu, Z, 4);                               \
        Z += __shfl_xor_sync(0xffffffffu, Z, 8);                               \
        Z += __shfl_xor_sync(0xffffffffu, Z, 16);                              \
        const float invZ = __fdividef(1.0f, Z);                                \
        _Pragma("unroll")                                                      \
        for (int q = 0; q < 4; q++) {                                          \
            const float cq = ce[q] * invZ;                                     \
            _Pragma("unroll")                                                  \
            for (int e = 0; e < 8; e++)                                        \
                sacc[8 * q + e] += cq * uf[8 * q + e];                         \
        }                                                                      \
    }

template <int NP>
__global__ void __launch_bounds__(256)
k_pass(const float* __restrict__ vin0, const float* __restrict__ vin1,
       float* __restrict__ sp) {
    const int b = blockIdx.y;
    const int w = threadIdx.x >> 5;
    const int t = threadIdx.x & 31;

    // v components at the same k-mapping as the u groups
    float vv[32];
#pragma unroll
    for (int q = 0; q < 4; q++) {
        float4 a = *reinterpret_cast<const float4*>(vin0 + (size_t)b * KK + 8 * t + 256 * q);
        float4 c4 = *reinterpret_cast<const float4*>(vin0 + (size_t)b * KK + 8 * t + 256 * q + 4);
        if (NP == 2) {
            float4 a1 = *reinterpret_cast<const float4*>(vin1 + (size_t)b * KK + 8 * t + 256 * q);
            float4 c1 = *reinterpret_cast<const float4*>(vin1 + (size_t)b * KK + 8 * t + 256 * q + 4);
            a.x += a1.x; a.y += a1.y; a.z += a1.z; a.w += a1.w;
            c4.x += c1.x; c4.y += c1.y; c4.z += c1.z; c4.w += c1.w;
        }
        vv[8 * q + 0] = a.x;  vv[8 * q + 1] = a.y;
        vv[8 * q + 2] = a.z;  vv[8 * q + 3] = a.w;
        vv[8 * q + 4] = c4.x; vv[8 * q + 5] = c4.y;
        vv[8 * q + 6] = c4.z; vv[8 * q + 7] = c4.w;
    }

    float sacc[32];
#pragma unroll
    for (int l = 0; l < 32; l++) sacc[l] = 0.f;

    const int jbase = blockIdx.x * 64 + w * 8;   // 8 warps x 8 j = 64 j / CTA
    const uint4* up = reinterpret_cast<const uint4*>(g_uh + ((size_t)b * NN + jbase) * KK);

    uint4 r0[4], r1[4];
#pragma unroll
    for (int q = 0; q < 4; q++) r0[q] = up[q * 32 + t];          // j0
#pragma unroll
    for (int q = 0; q < 4; q++) r1[q] = up[128 + q * 32 + t];    // j1

    for (int jb = 0; jb < 8; jb += 2) {
        PASS_BODY(r0, jb)
        PASS_BODY(r1, jb + 1)
    }

    // CTA reduction across the 8 warps (natural k layout)
    __shared__ float red[8][1032];     // 1032: keeps rows 16B-aligned, shifts banks
#pragma unroll
    for (int q = 0; q < 4; q++) {
        *reinterpret_cast<float4*>(&red[w][8 * t + 256 * q])     =
            make_float4(sacc[8 * q + 0], sacc[8 * q + 1], sacc[8 * q + 2], sacc[8 * q + 3]);
        *reinterpret_cast<float4*>(&red[w][8 * t + 256 * q + 4]) =
            make_float4(sacc[8 * q + 4], sacc[8 * q + 5], sacc[8 * q + 6], sacc[8 * q + 7]);
    }
    __syncthreads();

    float4 s = make_float4(0.f, 0.f, 0.f, 0.f);
#pragma unroll
    for (int ww = 0; ww < 8; ww++) {
        float4 p = *reinterpret_cast<const float4*>(&red[ww][4 * threadIdx.x]);
        s.x += p.x; s.y += p.y; s.z += p.z; s.w += p.w;
    }
    *reinterpret_cast<float4*>(sp + ((size_t)b * PCH + blockIdx.x) * KK + 4 * threadIdx.x) = s;
}

// Finalize: reduce NCH chunk partials + biases, squash -> v.
// One CTA (8 warps) per (b,c) for memory-level parallelism on the reduction.
template <int NCH>
__global__ void __launch_bounds__(256)
k_fin(const float* __restrict__ sp, const float* __restrict__ biases,
      float* __restrict__ vout) {
    const int bc = blockIdx.x;
    const int b = bc >> 5, c = bc & 31;
    const int w = threadIdx.x >> 5, lane = threadIdx.x & 31;

    float s = 0.f;
    const float* p = sp + (size_t)b * NCH * KK + c * LL + lane;
#pragma unroll 8
    for (int n = w; n < NCH; n += 8) s += p[(size_t)n * KK];

    __shared__ float red[8][32];
    red[w][lane] = s;
    __syncthreads();

    if (w == 0) {
        float v = biases[c * LL + lane];
#pragma unroll
        for (int ww = 0; ww < 8; ww++) v += red[ww][lane];
        float n2 = v * v;
#pragma unroll
        for (int o = 16; o; o >>= 1) n2 += __shfl_xor_sync(0xffffffffu, n2, o);
        const float nn = sqrtf(n2);
        const float f = n2 / (1.0f + n2) / (nn + 1e-7f);   // squash factor
        vout[(size_t)b * KK + c * LL + lane] = f * v;
    }
}

extern "C" void kernel_launch(void* const* d_in, const int* in_sizes, int n_in,
                              void* d_out, int out_size) {
    const float* x      = (const float*)d_in[0];  // [32,8,8,32,32] = [B,N,iL]
    const float* Wt     = (const float*)d_in[1];  // [2048,32,1024]
    const float* biases = (const float*)d_in[2];  // [32,32]
    float* out = (float*)d_out;                   // [32,32,32]

    float *s0p, *sp, *v0, *v1, *dm;
    cudaGetSymbolAddress((void**)&s0p, g_s0p);
    cudaGetSymbolAddress((void**)&sp,  g_sp);
    cudaGetSymbolAddress((void**)&v0,  g_v0);
    cudaGetSymbolAddress((void**)&v1,  g_v1);
    cudaGetSymbolAddress((void**)&dm,  g_dummy);

    k_dummy<<<1, 32>>>(dm);                              // launch 0 (ncu shim)
    k1<<<dim3(NCH1, 4), 256>>>(x, Wt);                   // launch 1
    k_fin<NCH1><<<BB * CC, 256>>>(s0p, biases, v0);      // launch 2
    k_pass<1><<<dim3(PCH, BB), 256>>>(v0, v0, sp);       // launch 3
    k_fin<PCH><<<BB * CC, 256>>>(sp, biases, v1);        // launch 4
    k_pass<2><<<dim3(PCH, BB), 256>>>(v0, v1, sp);       // launch 5
    k_fin<PCH><<<BB * CC, 256>>>(sp, biases, out);       // launch 6
}